// round 15
// baseline (speedup 1.0000x reference)
#include <cuda_runtime.h>
#include <cuda_bf16.h>
#include <math.h>
#include <stdint.h>

#define NN 100000
#define EE 1600000
#define D  128
#define HEADS 4
#define CH 32
#define NEG_SLOPE 0.2f
#define CAP 64                         // deg ~ Poisson(16); P(deg>64) ~ 1e-22
#define NB_SCAN ((NN + 1023) / 1024)   // 98 blocks (single wave)

// ---------------- scratch ------------------------------------------------------
__device__ float g_hf[NN * D];            // fp32 gather source (layer 1, then layer 2)
__device__ __nv_bfloat16 g_hb2[NN * D];   // relu(h1) bf16 (GEMM2 input)
__device__ float g_xr[NN * D];
__device__ float g_ss[NN * HEADS];
__device__ float g_sd[NN * HEADS];
__device__ int   g_deg[NN];
__device__ int   g_offs[NN + 1];
__device__ int   g_cursor[NN];
__device__ int   g_sorted_src[EE];
__device__ int   g_bsum[NB_SCAN];
__device__ unsigned g_bar_count = 0;
__device__ volatile unsigned g_bar_gen = 0;

__device__ __forceinline__ void gbar_scan() {
    __syncthreads();
    if (threadIdx.x == 0) {
        __threadfence();
        unsigned gen = g_bar_gen;
        if (atomicAdd(&g_bar_count, 1u) == NB_SCAN - 1) {
            g_bar_count = 0;
            __threadfence();
            g_bar_gen = gen + 1;
        } else {
            while (g_bar_gen == gen) { }
        }
        __threadfence();
    }
    __syncthreads();
}

// ---------------- edge dtype detection (per-block inline) -----------------------
__device__ __forceinline__ int detect_s64(const void* ei, int* smem_flag) {
    if (threadIdx.x == 0) *smem_flag = 1;
    __syncthreads();
    if (threadIdx.x < 256)
        if (((const unsigned int*)ei)[2 * threadIdx.x + 1] != 0u) *smem_flag = 0;
    __syncthreads();
    return *smem_flag;
}

// ---------------- count + scan fused (98 blocks, single wave) --------------------
__global__ void __launch_bounds__(256) countscan_kernel(const void* __restrict__ ei) {
    __shared__ int sm[256];
    __shared__ int blockpre;
    __shared__ int s64s;
    int s64 = detect_s64(ei, &s64s);

    const int b = blockIdx.x, tid = threadIdx.x;
    const int gt = b * 256 + tid;
    const int gsize = NB_SCAN * 256;

    if (s64) {
        const long long* e64 = (const long long*)ei;
        for (int i = gt; i < EE; i += gsize)
            atomicAdd(&g_deg[(int)e64[(long long)EE + i]], 1);
    } else {
        const int* e32 = (const int*)ei;
        for (int i = gt; i < EE; i += gsize)
            atomicAdd(&g_deg[e32[EE + i]], 1);
    }
    gbar_scan();

    int base = b * 1024 + tid * 4;
    int v[4];
#pragma unroll
    for (int j = 0; j < 4; ++j) {
        int idx = base + j;
        v[j] = (idx < NN) ? g_deg[idx] : 0;
    }
    int tot = v[0] + v[1] + v[2] + v[3];
    sm[tid] = tot;
    __syncthreads();
    for (int off = 128; off; off >>= 1) {
        if (tid < off) sm[tid] += sm[tid + off];
        __syncthreads();
    }
    if (tid == 0) g_bsum[b] = sm[0];

    gbar_scan();

    if (tid == 0) {
        int p = 0;
        for (int i = 0; i < b; ++i) p += g_bsum[i];
        blockpre = p;
    }
    sm[tid] = tot;
    __syncthreads();
    for (int off = 1; off < 256; off <<= 1) {
        int x = (tid >= off) ? sm[tid - off] : 0;
        __syncthreads();
        sm[tid] += x;
        __syncthreads();
    }
    int run = blockpre + ((tid == 0) ? 0 : sm[tid - 1]);
#pragma unroll
    for (int j = 0; j < 4; ++j) {
        int idx = base + j;
        if (idx < NN) {
            g_offs[idx]   = run;
            g_cursor[idx] = run;
            run += v[j];
        }
    }
    if (b == 0 && tid == 0) g_offs[NN] = EE;
}

__global__ void __launch_bounds__(256) scatter_kernel(const void* __restrict__ ei) {
    __shared__ int s64s;
    int s64 = detect_s64(ei, &s64s);
    int i = blockIdx.x * blockDim.x + threadIdx.x;
    if (i >= EE) return;
    int s, d;
    if (s64) {
        s = (int)((const long long*)ei)[i];
        d = (int)((const long long*)ei)[(long long)EE + i];
    } else {
        s = ((const int*)ei)[i];
        d = ((const int*)ei)[EE + i];
    }
    int pos = atomicAdd(&g_cursor[d], 1);
    g_sorted_src[pos] = s;
}

// ---------------- tf32 MMA helpers ------------------------------------------------
__device__ __forceinline__ uint32_t to_tf32u(float x) {
    uint32_t u;
    asm("cvt.rna.tf32.f32 %0, %1;" : "=r"(u) : "f"(x));
    return u;
}
__device__ __forceinline__ void cp16(uint32_t smem_dst, const void* gsrc) {
    asm volatile("cp.async.cg.shared.global [%0], [%1], 16;\n"
                 :: "r"(smem_dst), "l"(gsrc));
}
#define CP_COMMIT()  asm volatile("cp.async.commit_group;\n" ::: "memory")
#define CP_WAIT_1()  asm volatile("cp.async.wait_group 1;\n" ::: "memory")
#define CP_WAIT_0()  asm volatile("cp.async.wait_group 0;\n" ::: "memory")

#define MMA_TF32(c, av, bv)                                                  \
    asm volatile(                                                            \
        "mma.sync.aligned.m16n8k8.row.col.f32.tf32.tf32.f32 "                \
        "{%0,%1,%2,%3},{%4,%5,%6,%7},{%8,%9},{%0,%1,%2,%3};"                 \
        : "+f"((c)[0]), "+f"((c)[1]), "+f"((c)[2]), "+f"((c)[3])             \
        : "r"((av)[0]), "r"((av)[1]), "r"((av)[2]), "r"((av)[3]),            \
          "r"((bv)[0]), "r"((bv)[1]))

#define KC 16
#define NCH (D / KC)

// ---- fp32-input GEMM: block 128x128, 256 thr, 2 CTAs/SM, cp.async pipeline ------
template<bool SCORES>
__global__ void __launch_bounds__(256, 2) gemm_tc_kernel(
    const float* __restrict__ A, const float* __restrict__ W,
    const float* __restrict__ a_src, const float* __restrict__ a_dst,
    float* __restrict__ outf,
    float* __restrict__ ssrc, float* __restrict__ sdst)
{
    __shared__ float As[2][128][20];
    __shared__ float Ws[2][KC][132];

    const int tid  = threadIdx.x;
    const int warp = tid >> 5, lane = tid & 31;
    const int g = lane >> 2, t = lane & 3;
    const int wm = warp >> 1;
    const int wn = warp & 1;
    const int m0 = wm * 32, n0 = wn * 64;
    const int row0 = blockIdx.x * 128;

    const uint32_t as_base = (uint32_t)__cvta_generic_to_shared(&As[0][0][0]);
    const uint32_t ws_base = (uint32_t)__cvta_generic_to_shared(&Ws[0][0][0]);

    float acc[2][8][4];
#pragma unroll
    for (int i = 0; i < 2; ++i)
#pragma unroll
        for (int j = 0; j < 8; ++j)
#pragma unroll
            for (int k = 0; k < 4; ++k) acc[i][j][k] = 0.f;

    auto load_stage = [&](int s, int kc) {
#pragma unroll
        for (int it = 0; it < 2; ++it) {
            int idx = tid + it * 256;
            int r = idx >> 2, q = idx & 3;
            int row = row0 + r;
            if (row >= NN) row = NN - 1;
            cp16(as_base + (uint32_t)(((s * 128 + r) * 20 + q * 4) * 4),
                 &A[(long long)row * D + kc + q * 4]);
            int kr = idx >> 5, c4 = idx & 31;
            cp16(ws_base + (uint32_t)(((s * KC + kr) * 132 + c4 * 4) * 4),
                 &W[(kc + kr) * D + c4 * 4]);
        }
    };

    load_stage(0, 0);
    CP_COMMIT();

    for (int c = 0; c < NCH; ++c) {
        const int cur = c & 1;
        if (c + 1 < NCH) {
            load_stage((c + 1) & 1, (c + 1) * KC);
            CP_COMMIT();
            CP_WAIT_1();
        } else {
            CP_WAIT_0();
        }
        __syncthreads();

#pragma unroll
        for (int ks = 0; ks < KC; ks += 8) {
            uint32_t a[2][4], b[8][2];
#pragma unroll
            for (int mt = 0; mt < 2; ++mt) {
                int row = m0 + mt * 16 + g;
                a[mt][0] = to_tf32u(As[cur][row][ks + t]);
                a[mt][1] = to_tf32u(As[cur][row + 8][ks + t]);
                a[mt][2] = to_tf32u(As[cur][row][ks + t + 4]);
                a[mt][3] = to_tf32u(As[cur][row + 8][ks + t + 4]);
            }
#pragma unroll
            for (int nt = 0; nt < 8; ++nt) {
                int nc = n0 + nt * 8 + g;
                b[nt][0] = to_tf32u(Ws[cur][ks + t][nc]);
                b[nt][1] = to_tf32u(Ws[cur][ks + t + 4][nc]);
            }
#pragma unroll
            for (int mt = 0; mt < 2; ++mt)
#pragma unroll
                for (int nt = 0; nt < 8; ++nt)
                    MMA_TF32(acc[mt][nt], a[mt], b[nt]);
        }
        __syncthreads();
    }

    const int h0 = 2 * wn, h1 = 2 * wn + 1;
    float2 asv[8], adv[8];
    if (SCORES) {
#pragma unroll
        for (int nt = 0; nt < 8; ++nt) {
            int head = (nt < 4) ? h0 : h1;
            int cch  = (nt & 3) * 8 + 2 * t;
            asv[nt] = make_float2(a_src[head * CH + cch], a_src[head * CH + cch + 1]);
            adv[nt] = make_float2(a_dst[head * CH + cch], a_dst[head * CH + cch + 1]);
        }
    }
#pragma unroll
    for (int mt = 0; mt < 2; ++mt) {
        int r_lo = row0 + m0 + mt * 16 + g;
        int r_hi = r_lo + 8;
        float sA_lo = 0.f, dA_lo = 0.f, sA_hi = 0.f, dA_hi = 0.f;
        float sB_lo = 0.f, dB_lo = 0.f, sB_hi = 0.f, dB_hi = 0.f;
#pragma unroll
        for (int nt = 0; nt < 8; ++nt) {
            int col = n0 + nt * 8 + 2 * t;
            float2 v_lo = make_float2(acc[mt][nt][0], acc[mt][nt][1]);
            float2 v_hi = make_float2(acc[mt][nt][2], acc[mt][nt][3]);
            if (r_lo < NN) *(float2*)&outf[(long long)r_lo * D + col] = v_lo;
            if (r_hi < NN) *(float2*)&outf[(long long)r_hi * D + col] = v_hi;
            if (SCORES) {
                float su_l = v_lo.x * asv[nt].x + v_lo.y * asv[nt].y;
                float du_l = v_lo.x * adv[nt].x + v_lo.y * adv[nt].y;
                float su_h = v_hi.x * asv[nt].x + v_hi.y * asv[nt].y;
                float du_h = v_hi.x * adv[nt].x + v_hi.y * adv[nt].y;
                if (nt < 4) { sA_lo += su_l; dA_lo += du_l; sA_hi += su_h; dA_hi += du_h; }
                else        { sB_lo += su_l; dB_lo += du_l; sB_hi += su_h; dB_hi += du_h; }
            }
        }
        if (SCORES) {
#pragma unroll
            for (int off = 1; off <= 2; off <<= 1) {
                sA_lo += __shfl_xor_sync(0xffffffffu, sA_lo, off);
                dA_lo += __shfl_xor_sync(0xffffffffu, dA_lo, off);
                sA_hi += __shfl_xor_sync(0xffffffffu, sA_hi, off);
                dA_hi += __shfl_xor_sync(0xffffffffu, dA_hi, off);
                sB_lo += __shfl_xor_sync(0xffffffffu, sB_lo, off);
                dB_lo += __shfl_xor_sync(0xffffffffu, dB_lo, off);
                sB_hi += __shfl_xor_sync(0xffffffffu, sB_hi, off);
                dB_hi += __shfl_xor_sync(0xffffffffu, dB_hi, off);
            }
            if (t == 0) {
                if (r_lo < NN) {
                    ssrc[r_lo * HEADS + h0] = sA_lo; sdst[r_lo * HEADS + h0] = dA_lo;
                    ssrc[r_lo * HEADS + h1] = sB_lo; sdst[r_lo * HEADS + h1] = dB_lo;
                }
                if (r_hi < NN) {
                    ssrc[r_hi * HEADS + h0] = sA_hi; sdst[r_hi * HEADS + h0] = dA_hi;
                    ssrc[r_hi * HEADS + h1] = sB_hi; sdst[r_hi * HEADS + h1] = dB_hi;
                }
            }
        }
    }
}

// ---- layer-2 GEMM: bf16 input, fp32 output + scores ------------------------------
__global__ void __launch_bounds__(256, 2) gemm_l2_kernel(
    const unsigned short* __restrict__ A,
    const float* __restrict__ W,
    const float* __restrict__ a_src, const float* __restrict__ a_dst,
    float* __restrict__ outf,
    float* __restrict__ ssrc, float* __restrict__ sdst)
{
    __shared__ unsigned short As[2][128][24];
    __shared__ float Ws[2][KC][132];

    const int tid  = threadIdx.x;
    const int warp = tid >> 5, lane = tid & 31;
    const int g = lane >> 2, t = lane & 3;
    const int wm = warp >> 1;
    const int wn = warp & 1;
    const int m0 = wm * 32, n0 = wn * 64;
    const int row0 = blockIdx.x * 128;

    const uint32_t as_base = (uint32_t)__cvta_generic_to_shared(&As[0][0][0]);
    const uint32_t ws_base = (uint32_t)__cvta_generic_to_shared(&Ws[0][0][0]);

    float acc[2][8][4];
#pragma unroll
    for (int i = 0; i < 2; ++i)
#pragma unroll
        for (int j = 0; j < 8; ++j)
#pragma unroll
            for (int k = 0; k < 4; ++k) acc[i][j][k] = 0.f;

    auto load_stage = [&](int s, int kc) {
        {
            int r = tid >> 1, q = tid & 1;
            int row = row0 + r; if (row >= NN) row = NN - 1;
            cp16(as_base + (uint32_t)(((s * 128 + r) * 24 + q * 8) * 2),
                 &A[(long long)row * D + kc + q * 8]);
        }
#pragma unroll
        for (int it = 0; it < 2; ++it) {
            int idx = tid + it * 256;
            int kr = idx >> 5, c4 = idx & 31;
            cp16(ws_base + (uint32_t)(((s * KC + kr) * 132 + c4 * 4) * 4),
                 &W[(kc + kr) * D + c4 * 4]);
        }
    };

    load_stage(0, 0);
    CP_COMMIT();

    for (int c = 0; c < NCH; ++c) {
        const int cur = c & 1;
        if (c + 1 < NCH) {
            load_stage((c + 1) & 1, (c + 1) * KC);
            CP_COMMIT();
            CP_WAIT_1();
        } else {
            CP_WAIT_0();
        }
        __syncthreads();

#pragma unroll
        for (int ks = 0; ks < KC; ks += 8) {
            uint32_t a[2][4], b[8][2];
#pragma unroll
            for (int mt = 0; mt < 2; ++mt) {
                int row = m0 + mt * 16 + g;
                a[mt][0] = ((uint32_t)As[cur][row][ks + t]) << 16;
                a[mt][1] = ((uint32_t)As[cur][row + 8][ks + t]) << 16;
                a[mt][2] = ((uint32_t)As[cur][row][ks + t + 4]) << 16;
                a[mt][3] = ((uint32_t)As[cur][row + 8][ks + t + 4]) << 16;
            }
#pragma unroll
            for (int nt = 0; nt < 8; ++nt) {
                int nc = n0 + nt * 8 + g;
                b[nt][0] = to_tf32u(Ws[cur][ks + t][nc]);
                b[nt][1] = to_tf32u(Ws[cur][ks + t + 4][nc]);
            }
#pragma unroll
            for (int mt = 0; mt < 2; ++mt)
#pragma unroll
                for (int nt = 0; nt < 8; ++nt)
                    MMA_TF32(acc[mt][nt], a[mt], b[nt]);
        }
        __syncthreads();
    }

    const int h0 = 2 * wn, h1 = 2 * wn + 1;
    float2 asv[8], adv[8];
#pragma unroll
    for (int nt = 0; nt < 8; ++nt) {
        int head = (nt < 4) ? h0 : h1;
        int cch  = (nt & 3) * 8 + 2 * t;
        asv[nt] = make_float2(a_src[head * CH + cch], a_src[head * CH + cch + 1]);
        adv[nt] = make_float2(a_dst[head * CH + cch], a_dst[head * CH + cch + 1]);
    }
#pragma unroll
    for (int mt = 0; mt < 2; ++mt) {
        int r_lo = row0 + m0 + mt * 16 + g;
        int r_hi = r_lo + 8;
        float sA_lo = 0.f, dA_lo = 0.f, sA_hi = 0.f, dA_hi = 0.f;
        float sB_lo = 0.f, dB_lo = 0.f, sB_hi = 0.f, dB_hi = 0.f;
#pragma unroll
        for (int nt = 0; nt < 8; ++nt) {
            int col = n0 + nt * 8 + 2 * t;
            float2 v_lo = make_float2(acc[mt][nt][0], acc[mt][nt][1]);
            float2 v_hi = make_float2(acc[mt][nt][2], acc[mt][nt][3]);
            if (r_lo < NN) *(float2*)&outf[(long long)r_lo * D + col] = v_lo;
            if (r_hi < NN) *(float2*)&outf[(long long)r_hi * D + col] = v_hi;
            float su_l = v_lo.x * asv[nt].x + v_lo.y * asv[nt].y;
            float du_l = v_lo.x * adv[nt].x + v_lo.y * adv[nt].y;
            float su_h = v_hi.x * asv[nt].x + v_hi.y * asv[nt].y;
            float du_h = v_hi.x * adv[nt].x + v_hi.y * adv[nt].y;
            if (nt < 4) { sA_lo += su_l; dA_lo += du_l; sA_hi += su_h; dA_hi += du_h; }
            else        { sB_lo += su_l; dB_lo += du_l; sB_hi += su_h; dB_hi += du_h; }
        }
#pragma unroll
        for (int off = 1; off <= 2; off <<= 1) {
            sA_lo += __shfl_xor_sync(0xffffffffu, sA_lo, off);
            dA_lo += __shfl_xor_sync(0xffffffffu, dA_lo, off);
            sA_hi += __shfl_xor_sync(0xffffffffu, sA_hi, off);
            dA_hi += __shfl_xor_sync(0xffffffffu, dA_hi, off);
            sB_lo += __shfl_xor_sync(0xffffffffu, sB_lo, off);
            dB_lo += __shfl_xor_sync(0xffffffffu, dB_lo, off);
            sB_hi += __shfl_xor_sync(0xffffffffu, sB_hi, off);
            dB_hi += __shfl_xor_sync(0xffffffffu, dB_hi, off);
        }
        if (t == 0) {
            if (r_lo < NN) {
                ssrc[r_lo * HEADS + h0] = sA_lo; sdst[r_lo * HEADS + h0] = dA_lo;
                ssrc[r_lo * HEADS + h1] = sB_lo; sdst[r_lo * HEADS + h1] = dB_lo;
            }
            if (r_hi < NN) {
                ssrc[r_hi * HEADS + h0] = sA_hi; sdst[r_hi * HEADS + h0] = dA_hi;
                ssrc[r_hi * HEADS + h1] = sB_hi; sdst[r_hi * HEADS + h1] = dB_hi;
            }
        }
    }
}

// ---------------- softmax + aggregation: fp32 gather, lean hot loop ---------------
__device__ __forceinline__ float lrelu(float v) { return v > 0.f ? v : NEG_SLOPE * v; }

template<int LAYER>
__global__ void __launch_bounds__(256) agg_kernel(
    const float* __restrict__ hf,
    const float* __restrict__ ss,
    const float* __restrict__ sd,
    const float* __restrict__ bias,
    float* __restrict__ outf,              // LAYER 2
    __nv_bfloat16* __restrict__ outb,      // LAYER 1
    const float* __restrict__ xr,
    const float* __restrict__ br)
{
    __shared__ float2 pse[8][HEADS][CAP];

    int warp = (blockIdx.x * blockDim.x + threadIdx.x) >> 5;
    int wip  = threadIdx.x >> 5;
    int lane = threadIdx.x & 31;
    if (warp >= NN) return;
    unsigned n = warp;
    int begin = g_offs[n], end = g_offs[n + 1];
    int deg = end - begin;
    if (LAYER == 2 && lane == 0) g_deg[n] = 0;   // reset for next replay

    const float4* __restrict__ ss4 = (const float4*)ss;

    float4 sdv = ((const float4*)sd)[n];
    float4 ssn = ss4[n];
    float es0 = __expf(lrelu(ssn.x + sdv.x));
    float es1 = __expf(lrelu(ssn.y + sdv.y));
    float es2 = __expf(lrelu(ssn.z + sdv.z));
    float es3 = __expf(lrelu(ssn.w + sdv.w));
    float d0 = 0.f, d1 = 0.f, d2 = 0.f, d3 = 0.f;

    int hd = lane >> 3;
    unsigned c0 = lane * 4;
    const float* __restrict__ hfc = hf + c0;   // per-lane base

    float ax, ay, az, aw;
    float inv_dh;

    if (deg <= CAP) {
        const int* __restrict__ srcp = g_sorted_src + begin;
        for (int i = lane; i < deg; i += 32) {
            unsigned s = (unsigned)srcp[i];
            float4 sv = ss4[s];
            float fs = __int_as_float((int)s);
            float e0 = __expf(lrelu(sv.x + sdv.x));
            float e1 = __expf(lrelu(sv.y + sdv.y));
            float e2 = __expf(lrelu(sv.z + sdv.z));
            float e3 = __expf(lrelu(sv.w + sdv.w));
            pse[wip][0][i] = make_float2(fs, e0);
            pse[wip][1][i] = make_float2(fs, e1);
            pse[wip][2][i] = make_float2(fs, e2);
            pse[wip][3][i] = make_float2(fs, e3);
            d0 += e0; d1 += e1; d2 += e2; d3 += e3;
        }
#pragma unroll
        for (int off = 16; off; off >>= 1) {
            d0 += __shfl_xor_sync(0xffffffffu, d0, off);
            d1 += __shfl_xor_sync(0xffffffffu, d1, off);
            d2 += __shfl_xor_sync(0xffffffffu, d2, off);
            d3 += __shfl_xor_sync(0xffffffffu, d3, off);
        }
        d0 += es0; d1 += es1; d2 += es2; d3 += es3;
        __syncwarp();

        float dh  = (hd == 0) ? d0 : (hd == 1) ? d1 : (hd == 2) ? d2 : d3;
        float esh = (hd == 0) ? es0 : (hd == 1) ? es1 : (hd == 2) ? es2 : es3;
        inv_dh = 1.f / dh;

        float4 hn = *(const float4*)(hfc + n * (unsigned)D);
        ax = esh * hn.x; ay = esh * hn.y; az = esh * hn.z; aw = esh * hn.w;

        const float2* __restrict__ pp = &pse[wip][hd][0];
#pragma unroll 8
        for (int i = 0; i < deg; ++i) {
            float2 p = pp[i];
            unsigned s = (unsigned)__float_as_int(p.x);
            float e = p.y;
            float4 hv = *(const float4*)(hfc + s * (unsigned)D);
            ax += e * hv.x; ay += e * hv.y; az += e * hv.z; aw += e * hv.w;
        }
    } else {
        // fallback (deg > CAP; statistically unreachable)
        for (int e = begin + lane; e < end; e += 32) {
            unsigned s = (unsigned)g_sorted_src[e];
            float4 sv = ss4[s];
            d0 += __expf(lrelu(sv.x + sdv.x));
            d1 += __expf(lrelu(sv.y + sdv.y));
            d2 += __expf(lrelu(sv.z + sdv.z));
            d3 += __expf(lrelu(sv.w + sdv.w));
        }
#pragma unroll
        for (int off = 16; off; off >>= 1) {
            d0 += __shfl_xor_sync(0xffffffffu, d0, off);
            d1 += __shfl_xor_sync(0xffffffffu, d1, off);
            d2 += __shfl_xor_sync(0xffffffffu, d2, off);
            d3 += __shfl_xor_sync(0xffffffffu, d3, off);
        }
        d0 += es0; d1 += es1; d2 += es2; d3 += es3;

        float dh  = (hd == 0) ? d0 : (hd == 1) ? d1 : (hd == 2) ? d2 : d3;
        float esh = (hd == 0) ? es0 : (hd == 1) ? es1 : (hd == 2) ? es2 : es3;
        float sdh = (hd == 0) ? sdv.x : (hd == 1) ? sdv.y : (hd == 2) ? sdv.z : sdv.w;
        inv_dh = 1.f / dh;

        float4 hn = *(const float4*)(hfc + n * (unsigned)D);
        ax = esh * hn.x; ay = esh * hn.y; az = esh * hn.z; aw = esh * hn.w;
        for (int e = begin; e < end; ++e) {
            unsigned s = (unsigned)g_sorted_src[e];
            float w = __expf(lrelu(ss[s * HEADS + hd] + sdh));
            float4 hv = *(const float4*)(hfc + s * (unsigned)D);
            ax += w * hv.x; ay += w * hv.y; az += w * hv.z; aw += w * hv.w;
        }
    }

    ax *= inv_dh; ay *= inv_dh; az *= inv_dh; aw *= inv_dh;

    float4 b = *(const float4*)(bias + c0);
    unsigned outoff = n * (unsigned)D + c0;
    if (LAYER == 1) {
        float ox = fmaxf(ax + b.x, 0.f), oy = fmaxf(ay + b.y, 0.f);
        float oz = fmaxf(az + b.z, 0.f), ow = fmaxf(aw + b.w, 0.f);
        __nv_bfloat162 p0 = __float22bfloat162_rn(make_float2(ox, oy));
        __nv_bfloat162 p1 = __float22bfloat162_rn(make_float2(oz, ow));
        uint2 u;
        u.x = *reinterpret_cast<uint32_t*>(&p0);
        u.y = *reinterpret_cast<uint32_t*>(&p1);
        *(uint2*)(outb + outoff) = u;
    } else {
        float4 r  = *(const float4*)(xr + outoff);
        float4 bb = *(const float4*)(br + c0);
        float4 o = make_float4(ax + b.x + r.x + bb.x, ay + b.y + r.y + bb.y,
                               az + b.z + r.z + bb.z, aw + b.w + r.w + bb.w);
        *(float4*)(outf + outoff) = o;
    }
}

// ---------------- launch: 3-stream DAG schedule ------------------------------------
extern "C" void kernel_launch(void* const* d_in, const int* in_sizes, int n_in,
                              void* d_out, int out_size) {
    const float* x   = (const float*)d_in[0];
    const void*  ei  = d_in[1];
    const float* W1  = (const float*)d_in[2];
    const float* a1s = (const float*)d_in[3];
    const float* a1d = (const float*)d_in[4];
    const float* b1  = (const float*)d_in[5];
    const float* W2  = (const float*)d_in[6];
    const float* a2s = (const float*)d_in[7];
    const float* a2d = (const float*)d_in[8];
    const float* b2  = (const float*)d_in[9];
    const float* Wr  = (const float*)d_in[10];
    const float* br  = (const float*)d_in[11];
    float* out = (float*)d_out;

    float* hf;   cudaGetSymbolAddress((void**)&hf, g_hf);
    float* xr;   cudaGetSymbolAddress((void**)&xr, g_xr);
    float* ssp;  cudaGetSymbolAddress((void**)&ssp, g_ss);
    float* sdp;  cudaGetSymbolAddress((void**)&sdp, g_sd);
    __nv_bfloat16* hb2; cudaGetSymbolAddress((void**)&hb2, g_hb2);

    static cudaStream_t s2 = nullptr, s3 = nullptr;
    static cudaEvent_t evFork = nullptr, evPre = nullptr, evG1 = nullptr, evWr = nullptr;
    if (s2 == nullptr) {
        cudaStreamCreateWithFlags(&s2, cudaStreamNonBlocking);
        cudaStreamCreateWithFlags(&s3, cudaStreamNonBlocking);
        cudaEventCreateWithFlags(&evFork, cudaEventDisableTiming);
        cudaEventCreateWithFlags(&evPre, cudaEventDisableTiming);
        cudaEventCreateWithFlags(&evG1, cudaEventDisableTiming);
        cudaEventCreateWithFlags(&evWr, cudaEventDisableTiming);
    }

    const int ggrid = (NN + 127) / 128;

    // fork preprocessing onto s2
    cudaEventRecord(evFork, 0);
    cudaStreamWaitEvent(s2, evFork, 0);
    countscan_kernel<<<NB_SCAN, 256, 0, s2>>>(ei);                       // 1
    scatter_kernel<<<(EE + 255) / 256, 256, 0, s2>>>(ei);                // 2
    cudaEventRecord(evPre, s2);

    // stream 0: layer-1 transform (fp32 out + scores)
    gemm_tc_kernel<true><<<ggrid, 256>>>(                                // 3
        x, W1, a1s, a1d, hf, ssp, sdp);
    cudaEventRecord(evG1, 0);

    // stream 0: layer-1 aggregation (profiled slot 4); writes bf16 hb2
    cudaStreamWaitEvent(0, evPre, 0);
    agg_kernel<1><<<(NN + 7) / 8, 256>>>(hf, ssp, sdp, b1, nullptr, hb2, // 4
                                         nullptr, nullptr);

    // s3: residual transform x@Wr hidden under agg1 (starts after gemm1)
    cudaStreamWaitEvent(s3, evG1, 0);
    gemm_tc_kernel<false><<<ggrid, 256, 0, s3>>>(                        // 5
        x, Wr, nullptr, nullptr, xr, nullptr, nullptr);
    cudaEventRecord(evWr, s3);

    // stream 0: layer-2 transform (bf16 in, fp32 out to hf) + final agg
    gemm_l2_kernel<<<ggrid, 256>>>((const unsigned short*)hb2, W2,       // 6
                                   a2s, a2d, hf, ssp, sdp);
    cudaStreamWaitEvent(0, evWr, 0);
    agg_kernel<2><<<(NN + 7) / 8, 256>>>(hf, ssp, sdp, b2, out, nullptr, // 7
                                         xr, br);
}

// round 16
// speedup vs baseline: 1.1782x; 1.1782x over previous
#include <cuda_runtime.h>
#include <cuda_bf16.h>
#include <math.h>
#include <stdint.h>

#define NN 100000
#define EE 1600000
#define D  128
#define HEADS 4
#define CH 32
#define NEG_SLOPE 0.2f
#define CAP 64                         // deg ~ Poisson(16); P(deg>64) ~ 1e-22
#define NB_SCAN ((NN + 1023) / 1024)   // 98 blocks (single wave)

// ---------------- scratch ------------------------------------------------------
__device__ __nv_bfloat16 g_hb[NN * D];    // bf16 gather source (layer 1, then 2)
__device__ __nv_bfloat16 g_hb2[NN * D];   // relu(h1) bf16 (GEMM2 input)
__device__ float g_xr[NN * D];
__device__ float g_ss[NN * HEADS];
__device__ float g_sd[NN * HEADS];
__device__ int   g_deg[NN];
__device__ int   g_offs[NN + 1];
__device__ int   g_cursor[NN];
__device__ int   g_sorted_src[EE];
__device__ int   g_bsum[NB_SCAN];
__device__ unsigned g_bar_count = 0;
__device__ volatile unsigned g_bar_gen = 0;

__device__ __forceinline__ void gbar_scan() {
    __syncthreads();
    if (threadIdx.x == 0) {
        __threadfence();
        unsigned gen = g_bar_gen;
        if (atomicAdd(&g_bar_count, 1u) == NB_SCAN - 1) {
            g_bar_count = 0;
            __threadfence();
            g_bar_gen = gen + 1;
        } else {
            while (g_bar_gen == gen) { }
        }
        __threadfence();
    }
    __syncthreads();
}

// ---------------- edge dtype detection (per-block inline) -----------------------
__device__ __forceinline__ int detect_s64(const void* ei, int* smem_flag) {
    if (threadIdx.x == 0) *smem_flag = 1;
    __syncthreads();
    if (threadIdx.x < 256)
        if (((const unsigned int*)ei)[2 * threadIdx.x + 1] != 0u) *smem_flag = 0;
    __syncthreads();
    return *smem_flag;
}

// ---------------- count + scan fused (98 blocks, single wave) --------------------
__global__ void __launch_bounds__(256) countscan_kernel(const void* __restrict__ ei) {
    __shared__ int sm[256];
    __shared__ int blockpre;
    __shared__ int s64s;
    int s64 = detect_s64(ei, &s64s);

    const int b = blockIdx.x, tid = threadIdx.x;
    const int gt = b * 256 + tid;
    const int gsize = NB_SCAN * 256;

    if (s64) {
        const long long* e64 = (const long long*)ei;
        for (int i = gt; i < EE; i += gsize)
            atomicAdd(&g_deg[(int)e64[(long long)EE + i]], 1);
    } else {
        const int* e32 = (const int*)ei;
        for (int i = gt; i < EE; i += gsize)
            atomicAdd(&g_deg[e32[EE + i]], 1);
    }
    gbar_scan();

    int base = b * 1024 + tid * 4;
    int v[4];
#pragma unroll
    for (int j = 0; j < 4; ++j) {
        int idx = base + j;
        v[j] = (idx < NN) ? g_deg[idx] : 0;
    }
    int tot = v[0] + v[1] + v[2] + v[3];
    sm[tid] = tot;
    __syncthreads();
    for (int off = 128; off; off >>= 1) {
        if (tid < off) sm[tid] += sm[tid + off];
        __syncthreads();
    }
    if (tid == 0) g_bsum[b] = sm[0];

    gbar_scan();

    if (tid == 0) {
        int p = 0;
        for (int i = 0; i < b; ++i) p += g_bsum[i];
        blockpre = p;
    }
    sm[tid] = tot;
    __syncthreads();
    for (int off = 1; off < 256; off <<= 1) {
        int x = (tid >= off) ? sm[tid - off] : 0;
        __syncthreads();
        sm[tid] += x;
        __syncthreads();
    }
    int run = blockpre + ((tid == 0) ? 0 : sm[tid - 1]);
#pragma unroll
    for (int j = 0; j < 4; ++j) {
        int idx = base + j;
        if (idx < NN) {
            g_offs[idx]   = run;
            g_cursor[idx] = run;
            run += v[j];
        }
    }
    if (b == 0 && tid == 0) g_offs[NN] = EE;
}

__global__ void __launch_bounds__(256) scatter_kernel(const void* __restrict__ ei) {
    __shared__ int s64s;
    int s64 = detect_s64(ei, &s64s);
    int i = blockIdx.x * blockDim.x + threadIdx.x;
    if (i >= EE) return;
    int s, d;
    if (s64) {
        s = (int)((const long long*)ei)[i];
        d = (int)((const long long*)ei)[(long long)EE + i];
    } else {
        s = ((const int*)ei)[i];
        d = ((const int*)ei)[EE + i];
    }
    int pos = atomicAdd(&g_cursor[d], 1);
    g_sorted_src[pos] = s;
}

// ---------------- tf32 MMA helpers ------------------------------------------------
__device__ __forceinline__ uint32_t to_tf32u(float x) {
    uint32_t u;
    asm("cvt.rna.tf32.f32 %0, %1;" : "=r"(u) : "f"(x));
    return u;
}
__device__ __forceinline__ void cp16(uint32_t smem_dst, const void* gsrc) {
    asm volatile("cp.async.cg.shared.global [%0], [%1], 16;\n"
                 :: "r"(smem_dst), "l"(gsrc));
}
#define CP_COMMIT()  asm volatile("cp.async.commit_group;\n" ::: "memory")
#define CP_WAIT_1()  asm volatile("cp.async.wait_group 1;\n" ::: "memory")
#define CP_WAIT_0()  asm volatile("cp.async.wait_group 0;\n" ::: "memory")

#define MMA_TF32(c, av, bv)                                                  \
    asm volatile(                                                            \
        "mma.sync.aligned.m16n8k8.row.col.f32.tf32.tf32.f32 "                \
        "{%0,%1,%2,%3},{%4,%5,%6,%7},{%8,%9},{%0,%1,%2,%3};"                 \
        : "+f"((c)[0]), "+f"((c)[1]), "+f"((c)[2]), "+f"((c)[3])             \
        : "r"((av)[0]), "r"((av)[1]), "r"((av)[2]), "r"((av)[3]),            \
          "r"((bv)[0]), "r"((bv)[1]))

#define KC 16
#define NCH (D / KC)

// ---- fp32-input GEMM: block 128x128, 256 thr, 2 CTAs/SM, cp.async pipeline ------
template<bool SCORES, bool BF16OUT, bool F32OUT>
__global__ void __launch_bounds__(256, 2) gemm_tc_kernel(
    const float* __restrict__ A, const float* __restrict__ W,
    const float* __restrict__ a_src, const float* __restrict__ a_dst,
    __nv_bfloat16* __restrict__ hb, float* __restrict__ outf,
    float* __restrict__ ssrc, float* __restrict__ sdst)
{
    __shared__ float As[2][128][20];
    __shared__ float Ws[2][KC][132];

    const int tid  = threadIdx.x;
    const int warp = tid >> 5, lane = tid & 31;
    const int g = lane >> 2, t = lane & 3;
    const int wm = warp >> 1;
    const int wn = warp & 1;
    const int m0 = wm * 32, n0 = wn * 64;
    const int row0 = blockIdx.x * 128;

    const uint32_t as_base = (uint32_t)__cvta_generic_to_shared(&As[0][0][0]);
    const uint32_t ws_base = (uint32_t)__cvta_generic_to_shared(&Ws[0][0][0]);

    float acc[2][8][4];
#pragma unroll
    for (int i = 0; i < 2; ++i)
#pragma unroll
        for (int j = 0; j < 8; ++j)
#pragma unroll
            for (int k = 0; k < 4; ++k) acc[i][j][k] = 0.f;

    auto load_stage = [&](int s, int kc) {
#pragma unroll
        for (int it = 0; it < 2; ++it) {
            int idx = tid + it * 256;
            int r = idx >> 2, q = idx & 3;
            int row = row0 + r;
            if (row >= NN) row = NN - 1;
            cp16(as_base + (uint32_t)(((s * 128 + r) * 20 + q * 4) * 4),
                 &A[(long long)row * D + kc + q * 4]);
            int kr = idx >> 5, c4 = idx & 31;
            cp16(ws_base + (uint32_t)(((s * KC + kr) * 132 + c4 * 4) * 4),
                 &W[(kc + kr) * D + c4 * 4]);
        }
    };

    load_stage(0, 0);
    CP_COMMIT();

    for (int c = 0; c < NCH; ++c) {
        const int cur = c & 1;
        if (c + 1 < NCH) {
            load_stage((c + 1) & 1, (c + 1) * KC);
            CP_COMMIT();
            CP_WAIT_1();
        } else {
            CP_WAIT_0();
        }
        __syncthreads();

#pragma unroll
        for (int ks = 0; ks < KC; ks += 8) {
            uint32_t a[2][4], b[8][2];
#pragma unroll
            for (int mt = 0; mt < 2; ++mt) {
                int row = m0 + mt * 16 + g;
                a[mt][0] = to_tf32u(As[cur][row][ks + t]);
                a[mt][1] = to_tf32u(As[cur][row + 8][ks + t]);
                a[mt][2] = to_tf32u(As[cur][row][ks + t + 4]);
                a[mt][3] = to_tf32u(As[cur][row + 8][ks + t + 4]);
            }
#pragma unroll
            for (int nt = 0; nt < 8; ++nt) {
                int nc = n0 + nt * 8 + g;
                b[nt][0] = to_tf32u(Ws[cur][ks + t][nc]);
                b[nt][1] = to_tf32u(Ws[cur][ks + t + 4][nc]);
            }
#pragma unroll
            for (int mt = 0; mt < 2; ++mt)
#pragma unroll
                for (int nt = 0; nt < 8; ++nt)
                    MMA_TF32(acc[mt][nt], a[mt], b[nt]);
        }
        __syncthreads();
    }

    const int h0 = 2 * wn, h1 = 2 * wn + 1;
    float2 asv[8], adv[8];
    if (SCORES) {
#pragma unroll
        for (int nt = 0; nt < 8; ++nt) {
            int head = (nt < 4) ? h0 : h1;
            int cch  = (nt & 3) * 8 + 2 * t;
            asv[nt] = make_float2(a_src[head * CH + cch], a_src[head * CH + cch + 1]);
            adv[nt] = make_float2(a_dst[head * CH + cch], a_dst[head * CH + cch + 1]);
        }
    }
#pragma unroll
    for (int mt = 0; mt < 2; ++mt) {
        int r_lo = row0 + m0 + mt * 16 + g;
        int r_hi = r_lo + 8;
        float sA_lo = 0.f, dA_lo = 0.f, sA_hi = 0.f, dA_hi = 0.f;
        float sB_lo = 0.f, dB_lo = 0.f, sB_hi = 0.f, dB_hi = 0.f;
#pragma unroll
        for (int nt = 0; nt < 8; ++nt) {
            int col = n0 + nt * 8 + 2 * t;
            float2 v_lo = make_float2(acc[mt][nt][0], acc[mt][nt][1]);
            float2 v_hi = make_float2(acc[mt][nt][2], acc[mt][nt][3]);
            if (BF16OUT) {
                if (r_lo < NN)
                    *(__nv_bfloat162*)&hb[(long long)r_lo * D + col] =
                        __float22bfloat162_rn(v_lo);
                if (r_hi < NN)
                    *(__nv_bfloat162*)&hb[(long long)r_hi * D + col] =
                        __float22bfloat162_rn(v_hi);
            }
            if (F32OUT) {
                if (r_lo < NN) *(float2*)&outf[(long long)r_lo * D + col] = v_lo;
                if (r_hi < NN) *(float2*)&outf[(long long)r_hi * D + col] = v_hi;
            }
            if (SCORES) {
                float su_l = v_lo.x * asv[nt].x + v_lo.y * asv[nt].y;
                float du_l = v_lo.x * adv[nt].x + v_lo.y * adv[nt].y;
                float su_h = v_hi.x * asv[nt].x + v_hi.y * asv[nt].y;
                float du_h = v_hi.x * adv[nt].x + v_hi.y * adv[nt].y;
                if (nt < 4) { sA_lo += su_l; dA_lo += du_l; sA_hi += su_h; dA_hi += du_h; }
                else        { sB_lo += su_l; dB_lo += du_l; sB_hi += su_h; dB_hi += du_h; }
            }
        }
        if (SCORES) {
#pragma unroll
            for (int off = 1; off <= 2; off <<= 1) {
                sA_lo += __shfl_xor_sync(0xffffffffu, sA_lo, off);
                dA_lo += __shfl_xor_sync(0xffffffffu, dA_lo, off);
                sA_hi += __shfl_xor_sync(0xffffffffu, sA_hi, off);
                dA_hi += __shfl_xor_sync(0xffffffffu, dA_hi, off);
                sB_lo += __shfl_xor_sync(0xffffffffu, sB_lo, off);
                dB_lo += __shfl_xor_sync(0xffffffffu, dB_lo, off);
                sB_hi += __shfl_xor_sync(0xffffffffu, sB_hi, off);
                dB_hi += __shfl_xor_sync(0xffffffffu, dB_hi, off);
            }
            if (t == 0) {
                if (r_lo < NN) {
                    ssrc[r_lo * HEADS + h0] = sA_lo; sdst[r_lo * HEADS + h0] = dA_lo;
                    ssrc[r_lo * HEADS + h1] = sB_lo; sdst[r_lo * HEADS + h1] = dB_lo;
                }
                if (r_hi < NN) {
                    ssrc[r_hi * HEADS + h0] = sA_hi; sdst[r_hi * HEADS + h0] = dA_hi;
                    ssrc[r_hi * HEADS + h1] = sB_hi; sdst[r_hi * HEADS + h1] = dB_hi;
                }
            }
        }
    }
}

// ---- layer-2 GEMM: bf16 input, bf16 output + scores ------------------------------
__global__ void __launch_bounds__(256, 2) gemm_l2_kernel(
    const unsigned short* __restrict__ A,
    const float* __restrict__ W,
    const float* __restrict__ a_src, const float* __restrict__ a_dst,
    __nv_bfloat16* __restrict__ hb,
    float* __restrict__ ssrc, float* __restrict__ sdst)
{
    __shared__ unsigned short As[2][128][24];
    __shared__ float Ws[2][KC][132];

    const int tid  = threadIdx.x;
    const int warp = tid >> 5, lane = tid & 31;
    const int g = lane >> 2, t = lane & 3;
    const int wm = warp >> 1;
    const int wn = warp & 1;
    const int m0 = wm * 32, n0 = wn * 64;
    const int row0 = blockIdx.x * 128;

    const uint32_t as_base = (uint32_t)__cvta_generic_to_shared(&As[0][0][0]);
    const uint32_t ws_base = (uint32_t)__cvta_generic_to_shared(&Ws[0][0][0]);

    float acc[2][8][4];
#pragma unroll
    for (int i = 0; i < 2; ++i)
#pragma unroll
        for (int j = 0; j < 8; ++j)
#pragma unroll
            for (int k = 0; k < 4; ++k) acc[i][j][k] = 0.f;

    auto load_stage = [&](int s, int kc) {
        {
            int r = tid >> 1, q = tid & 1;
            int row = row0 + r; if (row >= NN) row = NN - 1;
            cp16(as_base + (uint32_t)(((s * 128 + r) * 24 + q * 8) * 2),
                 &A[(long long)row * D + kc + q * 8]);
        }
#pragma unroll
        for (int it = 0; it < 2; ++it) {
            int idx = tid + it * 256;
            int kr = idx >> 5, c4 = idx & 31;
            cp16(ws_base + (uint32_t)(((s * KC + kr) * 132 + c4 * 4) * 4),
                 &W[(kc + kr) * D + c4 * 4]);
        }
    };

    load_stage(0, 0);
    CP_COMMIT();

    for (int c = 0; c < NCH; ++c) {
        const int cur = c & 1;
        if (c + 1 < NCH) {
            load_stage((c + 1) & 1, (c + 1) * KC);
            CP_COMMIT();
            CP_WAIT_1();
        } else {
            CP_WAIT_0();
        }
        __syncthreads();

#pragma unroll
        for (int ks = 0; ks < KC; ks += 8) {
            uint32_t a[2][4], b[8][2];
#pragma unroll
            for (int mt = 0; mt < 2; ++mt) {
                int row = m0 + mt * 16 + g;
                a[mt][0] = ((uint32_t)As[cur][row][ks + t]) << 16;
                a[mt][1] = ((uint32_t)As[cur][row + 8][ks + t]) << 16;
                a[mt][2] = ((uint32_t)As[cur][row][ks + t + 4]) << 16;
                a[mt][3] = ((uint32_t)As[cur][row + 8][ks + t + 4]) << 16;
            }
#pragma unroll
            for (int nt = 0; nt < 8; ++nt) {
                int nc = n0 + nt * 8 + g;
                b[nt][0] = to_tf32u(Ws[cur][ks + t][nc]);
                b[nt][1] = to_tf32u(Ws[cur][ks + t + 4][nc]);
            }
#pragma unroll
            for (int mt = 0; mt < 2; ++mt)
#pragma unroll
                for (int nt = 0; nt < 8; ++nt)
                    MMA_TF32(acc[mt][nt], a[mt], b[nt]);
        }
        __syncthreads();
    }

    const int h0 = 2 * wn, h1 = 2 * wn + 1;
    float2 asv[8], adv[8];
#pragma unroll
    for (int nt = 0; nt < 8; ++nt) {
        int head = (nt < 4) ? h0 : h1;
        int cch  = (nt & 3) * 8 + 2 * t;
        asv[nt] = make_float2(a_src[head * CH + cch], a_src[head * CH + cch + 1]);
        adv[nt] = make_float2(a_dst[head * CH + cch], a_dst[head * CH + cch + 1]);
    }
#pragma unroll
    for (int mt = 0; mt < 2; ++mt) {
        int r_lo = row0 + m0 + mt * 16 + g;
        int r_hi = r_lo + 8;
        float sA_lo = 0.f, dA_lo = 0.f, sA_hi = 0.f, dA_hi = 0.f;
        float sB_lo = 0.f, dB_lo = 0.f, sB_hi = 0.f, dB_hi = 0.f;
#pragma unroll
        for (int nt = 0; nt < 8; ++nt) {
            int col = n0 + nt * 8 + 2 * t;
            float2 v_lo = make_float2(acc[mt][nt][0], acc[mt][nt][1]);
            float2 v_hi = make_float2(acc[mt][nt][2], acc[mt][nt][3]);
            if (r_lo < NN)
                *(__nv_bfloat162*)&hb[(long long)r_lo * D + col] =
                    __float22bfloat162_rn(v_lo);
            if (r_hi < NN)
                *(__nv_bfloat162*)&hb[(long long)r_hi * D + col] =
                    __float22bfloat162_rn(v_hi);
            float su_l = v_lo.x * asv[nt].x + v_lo.y * asv[nt].y;
            float du_l = v_lo.x * adv[nt].x + v_lo.y * adv[nt].y;
            float su_h = v_hi.x * asv[nt].x + v_hi.y * asv[nt].y;
            float du_h = v_hi.x * adv[nt].x + v_hi.y * adv[nt].y;
            if (nt < 4) { sA_lo += su_l; dA_lo += du_l; sA_hi += su_h; dA_hi += du_h; }
            else        { sB_lo += su_l; dB_lo += du_l; sB_hi += su_h; dB_hi += du_h; }
        }
#pragma unroll
        for (int off = 1; off <= 2; off <<= 1) {
            sA_lo += __shfl_xor_sync(0xffffffffu, sA_lo, off);
            dA_lo += __shfl_xor_sync(0xffffffffu, dA_lo, off);
            sA_hi += __shfl_xor_sync(0xffffffffu, sA_hi, off);
            dA_hi += __shfl_xor_sync(0xffffffffu, dA_hi, off);
            sB_lo += __shfl_xor_sync(0xffffffffu, sB_lo, off);
            dB_lo += __shfl_xor_sync(0xffffffffu, dB_lo, off);
            sB_hi += __shfl_xor_sync(0xffffffffu, sB_hi, off);
            dB_hi += __shfl_xor_sync(0xffffffffu, dB_hi, off);
        }
        if (t == 0) {
            if (r_lo < NN) {
                ssrc[r_lo * HEADS + h0] = sA_lo; sdst[r_lo * HEADS + h0] = dA_lo;
                ssrc[r_lo * HEADS + h1] = sB_lo; sdst[r_lo * HEADS + h1] = dB_lo;
            }
            if (r_hi < NN) {
                ssrc[r_hi * HEADS + h0] = sA_hi; sdst[r_hi * HEADS + h0] = dA_hi;
                ssrc[r_hi * HEADS + h1] = sB_hi; sdst[r_hi * HEADS + h1] = dB_hi;
            }
        }
    }
}

// ---------------- softmax + aggregation: bf16 gather, bit-op unpack ---------------
__device__ __forceinline__ float lrelu(float v) { return v > 0.f ? v : NEG_SLOPE * v; }

// exact bf16->fp32 via bit ops (2 ALU per packed pair)
__device__ __forceinline__ void unpack2(uint32_t u, float& lo, float& hi) {
    lo = __uint_as_float(u << 16);
    hi = __uint_as_float(u & 0xffff0000u);
}

template<int LAYER>
__global__ void __launch_bounds__(256) agg_kernel(
    const __nv_bfloat16* __restrict__ hb,
    const float* __restrict__ ss,
    const float* __restrict__ sd,
    const float* __restrict__ bias,
    float* __restrict__ outf,              // LAYER 2
    __nv_bfloat16* __restrict__ outb,      // LAYER 1
    const float* __restrict__ xr,
    const float* __restrict__ br)
{
    __shared__ float2 pse[8][HEADS][CAP];

    int warp = (blockIdx.x * blockDim.x + threadIdx.x) >> 5;
    int wip  = threadIdx.x >> 5;
    int lane = threadIdx.x & 31;
    if (warp >= NN) return;
    unsigned n = warp;
    int begin = g_offs[n], end = g_offs[n + 1];
    int deg = end - begin;
    if (LAYER == 2 && lane == 0) g_deg[n] = 0;   // reset for next replay

    const float4* __restrict__ ss4 = (const float4*)ss;

    float4 sdv = ((const float4*)sd)[n];
    float4 ssn = ss4[n];
    float es0 = __expf(lrelu(ssn.x + sdv.x));
    float es1 = __expf(lrelu(ssn.y + sdv.y));
    float es2 = __expf(lrelu(ssn.z + sdv.z));
    float es3 = __expf(lrelu(ssn.w + sdv.w));
    float d0 = 0.f, d1 = 0.f, d2 = 0.f, d3 = 0.f;

    int hd = lane >> 3;
    unsigned c0 = lane * 4;
    const __nv_bfloat16* __restrict__ hbc = hb + c0;   // per-lane base

    auto gather4 = [&](unsigned s, float& vx, float& vy, float& vz, float& vw) {
        uint2 u = *(const uint2*)(hbc + s * (unsigned)D);
        unpack2(u.x, vx, vy);
        unpack2(u.y, vz, vw);
    };

    float ax, ay, az, aw;
    float inv_dh;

    if (deg <= CAP) {
        const int* __restrict__ srcp = g_sorted_src + begin;
        for (int i = lane; i < deg; i += 32) {
            unsigned s = (unsigned)srcp[i];
            float4 sv = ss4[s];
            float fs = __int_as_float((int)s);
            float e0 = __expf(lrelu(sv.x + sdv.x));
            float e1 = __expf(lrelu(sv.y + sdv.y));
            float e2 = __expf(lrelu(sv.z + sdv.z));
            float e3 = __expf(lrelu(sv.w + sdv.w));
            pse[wip][0][i] = make_float2(fs, e0);
            pse[wip][1][i] = make_float2(fs, e1);
            pse[wip][2][i] = make_float2(fs, e2);
            pse[wip][3][i] = make_float2(fs, e3);
            d0 += e0; d1 += e1; d2 += e2; d3 += e3;
        }
#pragma unroll
        for (int off = 16; off; off >>= 1) {
            d0 += __shfl_xor_sync(0xffffffffu, d0, off);
            d1 += __shfl_xor_sync(0xffffffffu, d1, off);
            d2 += __shfl_xor_sync(0xffffffffu, d2, off);
            d3 += __shfl_xor_sync(0xffffffffu, d3, off);
        }
        d0 += es0; d1 += es1; d2 += es2; d3 += es3;
        __syncwarp();

        float dh  = (hd == 0) ? d0 : (hd == 1) ? d1 : (hd == 2) ? d2 : d3;
        float esh = (hd == 0) ? es0 : (hd == 1) ? es1 : (hd == 2) ? es2 : es3;
        inv_dh = 1.f / dh;

        float hx, hy, hz, hw;
        gather4(n, hx, hy, hz, hw);
        ax = esh * hx; ay = esh * hy; az = esh * hz; aw = esh * hw;

        const float2* __restrict__ pp = &pse[wip][hd][0];
#pragma unroll 4
        for (int i = 0; i < deg; ++i) {
            float2 p = pp[i];
            unsigned s = (unsigned)__float_as_int(p.x);
            float e = p.y;
            float vx, vy, vz, vw;
            gather4(s, vx, vy, vz, vw);
            ax += e * vx; ay += e * vy; az += e * vz; aw += e * vw;
        }
    } else {
        // fallback (deg > CAP; statistically unreachable)
        for (int e = begin + lane; e < end; e += 32) {
            unsigned s = (unsigned)g_sorted_src[e];
            float4 sv = ss4[s];
            d0 += __expf(lrelu(sv.x + sdv.x));
            d1 += __expf(lrelu(sv.y + sdv.y));
            d2 += __expf(lrelu(sv.z + sdv.z));
            d3 += __expf(lrelu(sv.w + sdv.w));
        }
#pragma unroll
        for (int off = 16; off; off >>= 1) {
            d0 += __shfl_xor_sync(0xffffffffu, d0, off);
            d1 += __shfl_xor_sync(0xffffffffu, d1, off);
            d2 += __shfl_xor_sync(0xffffffffu, d2, off);
            d3 += __shfl_xor_sync(0xffffffffu, d3, off);
        }
        d0 += es0; d1 += es1; d2 += es2; d3 += es3;

        float dh  = (hd == 0) ? d0 : (hd == 1) ? d1 : (hd == 2) ? d2 : d3;
        float esh = (hd == 0) ? es0 : (hd == 1) ? es1 : (hd == 2) ? es2 : es3;
        float sdh = (hd == 0) ? sdv.x : (hd == 1) ? sdv.y : (hd == 2) ? sdv.z : sdv.w;
        inv_dh = 1.f / dh;

        float hx, hy, hz, hw;
        gather4(n, hx, hy, hz, hw);
        ax = esh * hx; ay = esh * hy; az = esh * hz; aw = esh * hw;
        for (int e = begin; e < end; ++e) {
            unsigned s = (unsigned)g_sorted_src[e];
            float w = __expf(lrelu(ss[s * HEADS + hd] + sdh));
            float vx, vy, vz, vw;
            gather4(s, vx, vy, vz, vw);
            ax += w * vx; ay += w * vy; az += w * vz; aw += w * vw;
        }
    }

    ax *= inv_dh; ay *= inv_dh; az *= inv_dh; aw *= inv_dh;

    float4 b = *(const float4*)(bias + c0);
    unsigned outoff = n * (unsigned)D + c0;
    if (LAYER == 1) {
        float ox = fmaxf(ax + b.x, 0.f), oy = fmaxf(ay + b.y, 0.f);
        float oz = fmaxf(az + b.z, 0.f), ow = fmaxf(aw + b.w, 0.f);
        __nv_bfloat162 p0 = __float22bfloat162_rn(make_float2(ox, oy));
        __nv_bfloat162 p1 = __float22bfloat162_rn(make_float2(oz, ow));
        uint2 u;
        u.x = *reinterpret_cast<uint32_t*>(&p0);
        u.y = *reinterpret_cast<uint32_t*>(&p1);
        *(uint2*)(outb + outoff) = u;
    } else {
        float4 r  = *(const float4*)(xr + outoff);
        float4 bb = *(const float4*)(br + c0);
        float4 o = make_float4(ax + b.x + r.x + bb.x, ay + b.y + r.y + bb.y,
                               az + b.z + r.z + bb.z, aw + b.w + r.w + bb.w);
        *(float4*)(outf + outoff) = o;
    }
}

// ---------------- launch: 3-stream DAG schedule ------------------------------------
extern "C" void kernel_launch(void* const* d_in, const int* in_sizes, int n_in,
                              void* d_out, int out_size) {
    const float* x   = (const float*)d_in[0];
    const void*  ei  = d_in[1];
    const float* W1  = (const float*)d_in[2];
    const float* a1s = (const float*)d_in[3];
    const float* a1d = (const float*)d_in[4];
    const float* b1  = (const float*)d_in[5];
    const float* W2  = (const float*)d_in[6];
    const float* a2s = (const float*)d_in[7];
    const float* a2d = (const float*)d_in[8];
    const float* b2  = (const float*)d_in[9];
    const float* Wr  = (const float*)d_in[10];
    const float* br  = (const float*)d_in[11];
    float* out = (float*)d_out;

    float* xr;   cudaGetSymbolAddress((void**)&xr, g_xr);
    float* ssp;  cudaGetSymbolAddress((void**)&ssp, g_ss);
    float* sdp;  cudaGetSymbolAddress((void**)&sdp, g_sd);
    __nv_bfloat16* hb;  cudaGetSymbolAddress((void**)&hb, g_hb);
    __nv_bfloat16* hb2; cudaGetSymbolAddress((void**)&hb2, g_hb2);

    static cudaStream_t s2 = nullptr, s3 = nullptr;
    static cudaEvent_t evFork = nullptr, evPre = nullptr, evG1 = nullptr, evWr = nullptr;
    if (s2 == nullptr) {
        cudaStreamCreateWithFlags(&s2, cudaStreamNonBlocking);
        cudaStreamCreateWithFlags(&s3, cudaStreamNonBlocking);
        cudaEventCreateWithFlags(&evFork, cudaEventDisableTiming);
        cudaEventCreateWithFlags(&evPre, cudaEventDisableTiming);
        cudaEventCreateWithFlags(&evG1, cudaEventDisableTiming);
        cudaEventCreateWithFlags(&evWr, cudaEventDisableTiming);
    }

    const int ggrid = (NN + 127) / 128;

    // fork preprocessing onto s2
    cudaEventRecord(evFork, 0);
    cudaStreamWaitEvent(s2, evFork, 0);
    countscan_kernel<<<NB_SCAN, 256, 0, s2>>>(ei);                       // 1
    scatter_kernel<<<(EE + 255) / 256, 256, 0, s2>>>(ei);                // 2
    cudaEventRecord(evPre, s2);

    // stream 0: layer-1 transform (bf16 + scores)
    gemm_tc_kernel<true, true, false><<<ggrid, 256>>>(                   // 3
        x, W1, a1s, a1d, hb, nullptr, ssp, sdp);
    cudaEventRecord(evG1, 0);

    // stream 0: layer-1 aggregation (profiled slot 4)
    cudaStreamWaitEvent(0, evPre, 0);
    agg_kernel<1><<<(NN + 7) / 8, 256>>>(hb, ssp, sdp, b1, nullptr, hb2, // 4
                                         nullptr, nullptr);

    // s3: residual transform x@Wr hidden under agg1 (starts after gemm1)
    cudaStreamWaitEvent(s3, evG1, 0);
    gemm_tc_kernel<false, false, true><<<ggrid, 256, 0, s3>>>(           // 5
        x, Wr, nullptr, nullptr, nullptr, xr, nullptr, nullptr);
    cudaEventRecord(evWr, s3);

    // stream 0: layer-2 transform, then final aggregation + residual
    gemm_l2_kernel<<<ggrid, 256>>>((const unsigned short*)hb2, W2,       // 6
                                   a2s, a2d, hb, ssp, sdp);
    cudaStreamWaitEvent(0, evWr, 0);
    agg_kernel<2><<<(NN + 7) / 8, 256>>>(hb, ssp, sdp, b2, out, nullptr, // 7
                                         xr, br);
}